// round 1
// baseline (speedup 1.0000x reference)
#include <cuda_runtime.h>
#include <math.h>

#define N_NODES 100000
#define N_EDGES 3200000
#define IN_DIM 256
#define EMB_DIM 64
#define BATCH 4096

// Scratch (device globals — no allocation allowed)
__device__ float g_xw[(size_t)N_NODES * EMB_DIM];   // X @ W
__device__ float g_h[(size_t)N_NODES * EMB_DIM];    // segment_sum -> tanh -> normalized emb (in place)
__device__ float g_acc[2];                          // [0] = sum(emb^2), [1] = bpr sum

// ---------------------------------------------------------------------------
// Kernel 1: xw = feats @ W   (100000x256 @ 256x64)
// Block = 256 threads computes a 64x64 output tile; per-thread 4x4 accumulators.
// ---------------------------------------------------------------------------
__global__ void gemm_kernel(const float* __restrict__ feats,
                            const float* __restrict__ W) {
    __shared__ float fs[64][64];  // feats tile [row][k]
    __shared__ float ws[64][64];  // W tile    [k][col]
    const int row0 = blockIdx.x * 64;
    const int tid  = threadIdx.x;
    const int lr   = tid >> 4;          // 0..15
    const int lc   = (tid & 15) << 2;   // 0,4,...,60

    float acc[4][4];
#pragma unroll
    for (int i = 0; i < 4; i++)
#pragma unroll
        for (int j = 0; j < 4; j++) acc[i][j] = 0.f;

    for (int kb = 0; kb < IN_DIM; kb += 64) {
#pragma unroll
        for (int rr = lr; rr < 64; rr += 16) {
            int grow = row0 + rr;
            float4 f = make_float4(0.f, 0.f, 0.f, 0.f);
            if (grow < N_NODES)
                f = *(const float4*)&feats[(size_t)grow * IN_DIM + kb + lc];
            *(float4*)&fs[rr][lc] = f;
            *(float4*)&ws[rr][lc] = *(const float4*)&W[(size_t)(kb + rr) * EMB_DIM + lc];
        }
        __syncthreads();
#pragma unroll 8
        for (int k = 0; k < 64; k++) {
            float4 b = *(float4*)&ws[k][lc];
#pragma unroll
            for (int i = 0; i < 4; i++) {
                float a = fs[lr * 4 + i][k];
                acc[i][0] += a * b.x;
                acc[i][1] += a * b.y;
                acc[i][2] += a * b.z;
                acc[i][3] += a * b.w;
            }
        }
        __syncthreads();
    }

#pragma unroll
    for (int i = 0; i < 4; i++) {
        int grow = row0 + lr * 4 + i;
        if (grow < N_NODES) {
            float4 o = make_float4(acc[i][0], acc[i][1], acc[i][2], acc[i][3]);
            *(float4*)&g_xw[(size_t)grow * EMB_DIM + lc] = o;
        }
    }
}

// ---------------------------------------------------------------------------
// Kernel 2: h[row] += val * xw[col]   over all edges (COO SpMM).
// 16 threads per edge; each thread handles one float4 chunk (4 dims).
// Vector red.global.add.v4.f32 -> 16 atomics per edge instead of 64.
// ---------------------------------------------------------------------------
__global__ void edge_kernel(const int* __restrict__ erow,
                            const int* __restrict__ ecol,
                            const float* __restrict__ evalv) {
    long long idx = (long long)blockIdx.x * blockDim.x + threadIdx.x;
    int e = (int)(idx >> 4);
    if (e >= N_EDGES) return;
    int c4 = ((int)idx & 15) << 2;

    int   col = ecol[e];
    int   row = erow[e];
    float val = evalv[e];

    const float4 v = *(const float4*)&g_xw[(size_t)col * EMB_DIM + c4];
    float* p = &g_h[(size_t)row * EMB_DIM + c4];
    asm volatile("red.global.add.v4.f32 [%0], {%1, %2, %3, %4};"
                 :: "l"(p), "f"(v.x * val), "f"(v.y * val),
                    "f"(v.z * val), "f"(v.w * val)
                 : "memory");
}

// ---------------------------------------------------------------------------
// Kernel 3: h = tanh(h); emb = l2_normalize(h) (in place); accumulate sum(emb^2).
// One warp per node row; each lane handles 2 dims (float2).
// ---------------------------------------------------------------------------
__global__ void norm_kernel() {
    int warp = (blockIdx.x * blockDim.x + threadIdx.x) >> 5;
    int lane = threadIdx.x & 31;
    __shared__ float ssum;
    if (threadIdx.x == 0) ssum = 0.f;
    __syncthreads();

    if (warp < N_NODES) {
        float2 v = *(float2*)&g_h[(size_t)warp * EMB_DIM + lane * 2];
        v.x = tanhf(v.x);
        v.y = tanhf(v.y);
        float sq = v.x * v.x + v.y * v.y;
#pragma unroll
        for (int o = 16; o > 0; o >>= 1) sq += __shfl_xor_sync(0xffffffffu, sq, o);
        float rs = rsqrtf(fmaxf(sq, 1e-12f));
        v.x *= rs;
        v.y *= rs;
        *(float2*)&g_h[(size_t)warp * EMB_DIM + lane * 2] = v;
        if (lane == 0) atomicAdd(&ssum, sq * rs * rs);  // = sum(emb^2) for this row
    }
    __syncthreads();
    if (threadIdx.x == 0) atomicAdd(&g_acc[0], ssum);
}

// ---------------------------------------------------------------------------
// Kernel 4: BPR loss over the batch. One warp per batch element.
// ---------------------------------------------------------------------------
__global__ void loss_kernel(const int* __restrict__ idx1,
                            const int* __restrict__ idx2,
                            const int* __restrict__ negi) {
    int b    = (blockIdx.x * blockDim.x + threadIdx.x) >> 5;
    int lane = threadIdx.x & 31;
    __shared__ float ssum;
    if (threadIdx.x == 0) ssum = 0.f;
    __syncthreads();

    if (b < BATCH) {
        int i1 = idx1[b], i2 = idx2[b], in_ = negi[b];
        float2 e1 = *(float2*)&g_h[(size_t)i1 * EMB_DIM + lane * 2];
        float2 e2 = *(float2*)&g_h[(size_t)i2 * EMB_DIM + lane * 2];
        float2 en = *(float2*)&g_h[(size_t)in_ * EMB_DIM + lane * 2];
        float dui = e1.x * e2.x + e1.y * e2.y;
        float duj = e1.x * en.x + e1.y * en.y;
#pragma unroll
        for (int o = 16; o > 0; o >>= 1) {
            dui += __shfl_xor_sync(0xffffffffu, dui, o);
            duj += __shfl_xor_sync(0xffffffffu, duj, o);
        }
        if (lane == 0) {
            // -log_sigmoid(dui - duj) = softplus(duj - dui), numerically stable
            float z = duj - dui;
            float term = fmaxf(z, 0.f) + log1pf(expf(-fabsf(z)));
            atomicAdd(&ssum, term);
        }
    }
    __syncthreads();
    if (threadIdx.x == 0) atomicAdd(&g_acc[1], ssum);
}

// ---------------------------------------------------------------------------
// Kernel 5: finalize scalar loss.
// ---------------------------------------------------------------------------
__global__ void final_kernel(float* __restrict__ out) {
    out[0] = (g_acc[1] + 1e-4f * 0.5f * g_acc[0]) / (float)BATCH;
}

extern "C" void kernel_launch(void* const* d_in, const int* in_sizes, int n_in,
                              void* d_out, int out_size) {
    const float* feats = (const float*)d_in[0];
    const float* W     = (const float*)d_in[1];
    const int*   erow  = (const int*)d_in[2];
    const int*   ecol  = (const int*)d_in[3];
    const float* evalv = (const float*)d_in[4];
    const int*   idx1  = (const int*)d_in[5];
    const int*   idx2  = (const int*)d_in[6];
    const int*   negi  = (const int*)d_in[7];

    void* hptr;
    void* accptr;
    cudaGetSymbolAddress(&hptr, g_h);
    cudaGetSymbolAddress(&accptr, g_acc);
    cudaMemsetAsync(hptr, 0, sizeof(float) * (size_t)N_NODES * EMB_DIM);
    cudaMemsetAsync(accptr, 0, sizeof(float) * 2);

    gemm_kernel<<<(N_NODES + 63) / 64, 256>>>(feats, W);

    // 16 threads per edge -> N_EDGES*16 = 51.2M threads
    edge_kernel<<<(int)(((long long)N_EDGES * 16) / 256), 256>>>(erow, ecol, evalv);

    norm_kernel<<<(N_NODES * 32 + 255) / 256, 256>>>();

    loss_kernel<<<(BATCH * 32) / 256, 256>>>(idx1, idx2, negi);

    final_kernel<<<1, 1>>>((float*)d_out);
}